// round 8
// baseline (speedup 1.0000x reference)
#include <cuda_runtime.h>
#include <cuda_fp16.h>
#include <cstdint>

// Problem constants
#define Bsz 2
#define SEQ 2048
#define EMB 2048
#define NH  32
#define NKV 8
#define HD  64
#define BSxS (Bsz*SEQ) // 4096

// ---------------- scratch ----------------------------------------------------
__device__ __half g_xh[(size_t)BSxS * EMB];           // x fp16
__device__ __half g_wqh[(size_t)EMB * EMB];
__device__ __half g_wkh[(size_t)EMB * NKV * HD];
__device__ __half g_wvh[(size_t)EMB * NKV * HD];
__device__ __half g_woh[(size_t)EMB * EMB];
__device__ __half g_qh[(size_t)BSxS * EMB];           // roped+scaled Q fp16 (B,S,H,D)
__device__ __half g_kh[(size_t)Bsz * NKV * SEQ * HD]; // roped K fp16 (B,KV,S,D)
__device__ __half g_vh[(size_t)Bsz * NKV * SEQ * HD]; // V fp16 (B,KV,S,D)
__device__ __half g_ah[(size_t)BSxS * EMB];           // attention out fp16

// ---------------- PTX helpers ------------------------------------------------
__device__ __forceinline__ uint32_t smem_u32(const void* p) {
    return (uint32_t)__cvta_generic_to_shared(p);
}
__device__ __forceinline__ void ldsm_x4(uint32_t& r0, uint32_t& r1, uint32_t& r2,
                                        uint32_t& r3, uint32_t addr) {
    asm volatile("ldmatrix.sync.aligned.m8n8.x4.shared.b16 {%0,%1,%2,%3},[%4];"
                 : "=r"(r0), "=r"(r1), "=r"(r2), "=r"(r3) : "r"(addr));
}
__device__ __forceinline__ void ldsm_x4t(uint32_t& r0, uint32_t& r1, uint32_t& r2,
                                         uint32_t& r3, uint32_t addr) {
    asm volatile("ldmatrix.sync.aligned.m8n8.x4.trans.shared.b16 {%0,%1,%2,%3},[%4];"
                 : "=r"(r0), "=r"(r1), "=r"(r2), "=r"(r3) : "r"(addr));
}
__device__ __forceinline__ void mma_f16(float c[4], uint32_t a0, uint32_t a1,
                                        uint32_t a2, uint32_t a3,
                                        uint32_t b0, uint32_t b1) {
    asm volatile(
        "mma.sync.aligned.m16n8k16.row.col.f32.f16.f16.f32 "
        "{%0,%1,%2,%3},{%4,%5,%6,%7},{%8,%9},{%0,%1,%2,%3};"
        : "+f"(c[0]), "+f"(c[1]), "+f"(c[2]), "+f"(c[3])
        : "r"(a0), "r"(a1), "r"(a2), "r"(a3), "r"(b0), "r"(b1));
}
__device__ __forceinline__ void st_half4(__half* p, float4 v) {
    __half2 h0 = __floats2half2_rn(v.x, v.y);
    __half2 h1 = __floats2half2_rn(v.z, v.w);
    uint2 u;
    u.x = *(uint32_t*)&h0;
    u.y = *(uint32_t*)&h1;
    *(uint2*)p = u;
}
__device__ __forceinline__ void cp16(uint32_t dst, const void* src) {
    asm volatile("cp.async.ca.shared.global [%0], [%1], 16;" :: "r"(dst), "l"(src));
}
__device__ __forceinline__ void cp_commit() {
    asm volatile("cp.async.commit_group;" ::: "memory");
}
template <int N>
__device__ __forceinline__ void cp_wait() {
    asm volatile("cp.async.wait_group %0;" :: "n"(N) : "memory");
}

// ---------------- merged fp32 -> fp16 conversions (5 segments) ---------------
__global__ void cvt5(const float* s0, __half* d0, int n0,
                     const float* s1, __half* d1, int n1,
                     const float* s2, __half* d2, int n2,
                     const float* s3, __half* d3, int n3,
                     const float* s4, __half* d4, int n4)
{
    const float* s; __half* d; int n;
    switch (blockIdx.y) {
        case 0: s = s0; d = d0; n = n0; break;
        case 1: s = s1; d = d1; n = n1; break;
        case 2: s = s2; d = d2; n = n2; break;
        case 3: s = s3; d = d3; n = n3; break;
        default: s = s4; d = d4; n = n4; break;
    }
    int stride = gridDim.x * blockDim.x * 4;
    for (int i = (blockIdx.x * blockDim.x + threadIdx.x) * 4; i < n; i += stride)
        st_half4(d + i, *(const float4*)(s + i));
}

// ---------------- fp16 cp.async pipelined GEMM with fused epilogues ----------
// MODE 0: plain fp32 C0.
// MODE 1: RoPE+1/8 scale -> fp16 H0 (Q projection; N=(H,D), warp n-tile = 1 head)
// MODE 2: z=0: RoPE + transpose -> fp32 C0 + fp16 H0 (K); z=1: transpose -> C1/H1 (V)
#define TM 128
#define TN 128
#define TK 32
#define AST 40
#define BST 136
#define STG 3
#define ASZ (TM * AST * 2)
#define BSZ (TK * BST * 2)

template <int MODE>
__global__ __launch_bounds__(256) void h16_gemm(
    const __half* __restrict__ A,
    const __half* __restrict__ B0, const __half* __restrict__ B1,
    float* __restrict__ C0, float* __restrict__ C1,
    __half* __restrict__ H0, __half* __restrict__ H1,
    const float* __restrict__ cosp, const float* __restrict__ sinp,
    int M, int N, int K)
{
    __shared__ __align__(16) __half As[STG][TM][AST];
    __shared__ __align__(16) __half Bs[STG][TK][BST];

    const __half* B = (blockIdx.z == 0) ? B0 : B1;

    int tid = threadIdx.x, lane = tid & 31, wid = tid >> 5;
    int wm = wid & 3, wn = wid >> 2;
    int g = lane >> 2, tg = lane & 3;

    const __half* Ab = A + (size_t)blockIdx.y * TM * K;
    const __half* Bb = B + (size_t)blockIdx.x * TN;

    float acc[2][8][4];
#pragma unroll
    for (int i = 0; i < 2; i++)
#pragma unroll
        for (int j = 0; j < 8; j++)
#pragma unroll
            for (int r = 0; r < 4; r++) acc[i][j][r] = 0.f;

    int ar0 = tid >> 2, ac0 = (tid & 3) * 8;
    int ar1 = (tid + 256) >> 2, ac1 = ((tid + 256) & 3) * 8;
    int br0 = tid >> 4, bc0 = (tid & 15) * 8;
    int br1 = (tid + 256) >> 4, bc1 = ((tid + 256) & 15) * 8;
    uint32_t aD0 = smem_u32(&As[0][ar0][ac0]);
    uint32_t aD1 = smem_u32(&As[0][ar1][ac1]);
    uint32_t bD0 = smem_u32(&Bs[0][br0][bc0]);
    uint32_t bD1 = smem_u32(&Bs[0][br1][bc1]);

    uint32_t aAddr[2], bAddr[4];
    {
        int arow = wm * 32 + (lane & 15);
        int acol = (lane >> 4) * 8;
        aAddr[0] = smem_u32(&As[0][arow][acol]);
        aAddr[1] = smem_u32(&As[0][arow + 16][acol]);
        int brow = ((lane >> 3) & 1) * 8 + (lane & 7);
        int bcol = wn * 64 + ((lane >> 4) & 1) * 8;
#pragma unroll
        for (int nb = 0; nb < 4; nb++)
            bAddr[nb] = smem_u32(&Bs[0][brow][bcol + nb * 16]);
    }

    int nt = K / TK;

#pragma unroll
    for (int p = 0; p < 2; p++) {
        int k0 = p * TK;
        cp16(aD0 + p * ASZ, Ab + (size_t)ar0 * K + k0 + ac0);
        cp16(aD1 + p * ASZ, Ab + (size_t)ar1 * K + k0 + ac1);
        cp16(bD0 + p * BSZ, Bb + (size_t)(k0 + br0) * N + bc0);
        cp16(bD1 + p * BSZ, Bb + (size_t)(k0 + br1) * N + bc1);
        cp_commit();
    }

    int st = 0;
    for (int t = 0; t < nt; t++) {
        cp_wait<1>();
        __syncthreads();

        uint32_t aOff = (uint32_t)(st * ASZ);
        uint32_t bOff = (uint32_t)(st * BSZ);
#pragma unroll
        for (int ks = 0; ks < 2; ks++) {
            uint32_t af[2][4];
            ldsm_x4(af[0][0], af[0][1], af[0][2], af[0][3], aAddr[0] + aOff + ks * 32);
            ldsm_x4(af[1][0], af[1][1], af[1][2], af[1][3], aAddr[1] + aOff + ks * 32);
            uint32_t bf[8][2];
#pragma unroll
            for (int nb = 0; nb < 4; nb++) {
                uint32_t r0, r1, r2, r3;
                ldsm_x4t(r0, r1, r2, r3, bAddr[nb] + bOff + ks * (16 * BST * 2));
                bf[2 * nb][0] = r0; bf[2 * nb][1] = r1;
                bf[2 * nb + 1][0] = r2; bf[2 * nb + 1][1] = r3;
            }
#pragma unroll
            for (int mf = 0; mf < 2; mf++)
#pragma unroll
                for (int fn = 0; fn < 8; fn++)
                    mma_f16(acc[mf][fn], af[mf][0], af[mf][1], af[mf][2], af[mf][3],
                            bf[fn][0], bf[fn][1]);
        }
        // single barrier per iteration: writes below target stage (st+2)%3,
        // whose last readers finished before this iteration's top barrier.
        if (t + 2 < nt) {
            int ns = (st + 2) % STG;
            int k0 = (t + 2) * TK;
            cp16(aD0 + ns * ASZ, Ab + (size_t)ar0 * K + k0 + ac0);
            cp16(aD1 + ns * ASZ, Ab + (size_t)ar1 * K + k0 + ac1);
            cp16(bD0 + ns * BSZ, Bb + (size_t)(k0 + br0) * N + bc0);
            cp16(bD1 + ns * BSZ, Bb + (size_t)(k0 + br1) * N + bc1);
        }
        cp_commit();
        st = (st + 1) % STG;
    }

    // ---------------- epilogues ----------------
    if (MODE == 0) {
#pragma unroll
        for (int mf = 0; mf < 2; mf++) {
            int row0 = blockIdx.y * TM + wm * 32 + mf * 16 + g;
#pragma unroll
            for (int fn = 0; fn < 8; fn++) {
                int col = blockIdx.x * TN + wn * 64 + fn * 8 + tg * 2;
                *(float2*)&C0[(size_t)row0 * N + col] =
                    make_float2(acc[mf][fn][0], acc[mf][fn][1]);
                *(float2*)&C0[(size_t)(row0 + 8) * N + col] =
                    make_float2(acc[mf][fn][2], acc[mf][fn][3]);
            }
        }
    } else if (MODE == 1) {
        // Q: RoPE + 1/8 scale, fp16 out. Pairs: acc[][fn] (d) with acc[][fn+4] (d+32).
        int colb = blockIdx.x * TN + wn * 64;
#pragma unroll
        for (int mf = 0; mf < 2; mf++) {
            int row0 = blockIdx.y * TM + wm * 32 + mf * 16 + g;
            int sA = row0 & (SEQ - 1);
            int sB = sA + 8;
#pragma unroll
            for (int fn = 0; fn < 4; fn++) {
                int d0 = fn * 8 + tg * 2;
                float2 cA = *(const float2*)&cosp[sA * HD + d0];
                float2 nA = *(const float2*)&sinp[sA * HD + d0];
                float2 cB = *(const float2*)&cosp[sB * HD + d0];
                float2 nB = *(const float2*)&sinp[sB * HD + d0];
                float x10 = acc[mf][fn][0], x11 = acc[mf][fn][1];
                float x20 = acc[mf][fn + 4][0], x21 = acc[mf][fn + 4][1];
                __half2 lo = __floats2half2_rn((x10 * cA.x - x20 * nA.x) * 0.125f,
                                               (x11 * cA.y - x21 * nA.y) * 0.125f);
                __half2 hi = __floats2half2_rn((x20 * cA.x + x10 * nA.x) * 0.125f,
                                               (x21 * cA.y + x11 * nA.y) * 0.125f);
                *(__half2*)&H0[(size_t)row0 * N + colb + d0]      = lo;
                *(__half2*)&H0[(size_t)row0 * N + colb + d0 + 32] = hi;
                x10 = acc[mf][fn][2]; x11 = acc[mf][fn][3];
                x20 = acc[mf][fn + 4][2]; x21 = acc[mf][fn + 4][3];
                lo = __floats2half2_rn((x10 * cB.x - x20 * nB.x) * 0.125f,
                                       (x11 * cB.y - x21 * nB.y) * 0.125f);
                hi = __floats2half2_rn((x20 * cB.x + x10 * nB.x) * 0.125f,
                                       (x21 * cB.y + x11 * nB.y) * 0.125f);
                *(__half2*)&H0[(size_t)(row0 + 8) * N + colb + d0]      = lo;
                *(__half2*)&H0[(size_t)(row0 + 8) * N + colb + d0 + 32] = hi;
            }
        }
    } else {
        // KV: transpose (B,S,KV,D)->(B,KV,S,D); z=0 rope (K), z=1 plain (V).
        float* Cz  = (blockIdx.z == 0) ? C0 : C1;
        __half* Hz = (blockIdx.z == 0) ? H0 : H1;
        bool dorope = (blockIdx.z == 0);
        int colb = blockIdx.x * TN + wn * 64;
        int kvh = colb >> 6;
#pragma unroll
        for (int mf = 0; mf < 2; mf++) {
            int row0 = blockIdx.y * TM + wm * 32 + mf * 16 + g;
            int sA = row0 & (SEQ - 1);
            int bA = row0 >> 11;
            size_t oA = (((size_t)bA * NKV + kvh) * SEQ + sA) * HD;
            size_t oB = oA + (size_t)8 * HD;
#pragma unroll
            for (int fn = 0; fn < 4; fn++) {
                int d0 = fn * 8 + tg * 2;
                float r0, r1, r2, r3, q0, q1, q2, q3;
                if (dorope) {
                    float2 cA = *(const float2*)&cosp[sA * HD + d0];
                    float2 nA = *(const float2*)&sinp[sA * HD + d0];
                    float2 cB = *(const float2*)&cosp[(sA + 8) * HD + d0];
                    float2 nB = *(const float2*)&sinp[(sA + 8) * HD + d0];
                    r0 = acc[mf][fn][0] * cA.x - acc[mf][fn + 4][0] * nA.x;
                    r1 = acc[mf][fn][1] * cA.y - acc[mf][fn + 4][1] * nA.y;
                    r2 = acc[mf][fn + 4][0] * cA.x + acc[mf][fn][0] * nA.x;
                    r3 = acc[mf][fn + 4][1] * cA.y + acc[mf][fn][1] * nA.y;
                    q0 = acc[mf][fn][2] * cB.x - acc[mf][fn + 4][2] * nB.x;
                    q1 = acc[mf][fn][3] * cB.y - acc[mf][fn + 4][3] * nB.y;
                    q2 = acc[mf][fn + 4][2] * cB.x + acc[mf][fn][2] * nB.x;
                    q3 = acc[mf][fn + 4][3] * cB.y + acc[mf][fn][3] * nB.y;
                } else {
                    r0 = acc[mf][fn][0]; r1 = acc[mf][fn][1];
                    r2 = acc[mf][fn + 4][0]; r3 = acc[mf][fn + 4][1];
                    q0 = acc[mf][fn][2]; q1 = acc[mf][fn][3];
                    q2 = acc[mf][fn + 4][2]; q3 = acc[mf][fn + 4][3];
                }
                *(float2*)&Cz[oA + d0]      = make_float2(r0, r1);
                *(float2*)&Cz[oA + d0 + 32] = make_float2(r2, r3);
                *(float2*)&Cz[oB + d0]      = make_float2(q0, q1);
                *(float2*)&Cz[oB + d0 + 32] = make_float2(q2, q3);
                *(__half2*)&Hz[oA + d0]      = __floats2half2_rn(r0, r1);
                *(__half2*)&Hz[oA + d0 + 32] = __floats2half2_rn(r2, r3);
                *(__half2*)&Hz[oB + d0]      = __floats2half2_rn(q0, q1);
                *(__half2*)&Hz[oB + d0 + 32] = __floats2half2_rn(q2, q3);
            }
        }
    }
}

// ---------------- Tensor-core flash attention (causal) -----------------------
// grid (S/128, NH, B), 256 threads. Longest blocks (high qt) launch first.
#define QTILE 128
#define KTILE 64
#define QST 72
#define KSTGB (KTILE * QST * 2)
#define ATTN_SMEM ((QTILE + 4 * KTILE) * QST * 2)  // 55296 B

__global__ __launch_bounds__(256) void attn_h16(
    const __half* __restrict__ q,
    const __half* __restrict__ kk,
    const __half* __restrict__ vv,
    __half* __restrict__ out)
{
    extern __shared__ __align__(16) __half sm[];
    __half (*Qh)[QST] = (__half(*)[QST])sm;
    __half (*Ks)[QST] = (__half(*)[QST])(sm + QTILE * QST);
    __half (*Vs)[QST] = (__half(*)[QST])(sm + (QTILE + 2 * KTILE) * QST);

    int qt = gridDim.x - 1 - blockIdx.x;   // longest work first
    int h = blockIdx.y, b = blockIdx.z;
    int kv = h >> 2;
    int tid = threadIdx.x, lane = tid & 31, w = tid >> 5;
    int g = lane >> 2, tg = lane & 3;

    const __half* qbase = q + (((size_t)b * SEQ + (size_t)qt * QTILE) * NH + h) * HD;
    const __half* kbase = kk + ((size_t)b * NKV + kv) * SEQ * HD;
    const __half* vbase = vv + ((size_t)b * NKV + kv) * SEQ * HD;

    int kr0 = tid >> 3, kc0 = (tid & 7) * 8;
    int kr1 = (tid + 256) >> 3, kc1 = ((tid + 256) & 7) * 8;
    uint32_t ksD0 = smem_u32(&Ks[kr0][kc0]), ksD1 = smem_u32(&Ks[kr1][kc1]);
    uint32_t vsD0 = smem_u32(&Vs[kr0][kc0]), vsD1 = smem_u32(&Vs[kr1][kc1]);

    int nk = 2 * qt + 2;

#pragma unroll
    for (int i = 0; i < 4; i++) {
        int c = tid + i * 256;
        int r = c >> 3, col = (c & 7) * 8;
        cp16(smem_u32(&Qh[r][col]), qbase + (size_t)r * NH * HD + col);
    }
    {
        cp16(ksD0, kbase + (size_t)kr0 * HD + kc0);
        cp16(ksD1, kbase + (size_t)kr1 * HD + kc1);
        cp16(vsD0, vbase + (size_t)kr0 * HD + kc0);
        cp16(vsD1, vbase + (size_t)kr1 * HD + kc1);
    }
    cp_commit();
    {
        const __half* kp = kbase + (size_t)KTILE * HD;
        const __half* vp = vbase + (size_t)KTILE * HD;
        cp16(ksD0 + KSTGB, kp + (size_t)kr0 * HD + kc0);
        cp16(ksD1 + KSTGB, kp + (size_t)kr1 * HD + kc1);
        cp16(vsD0 + KSTGB, vp + (size_t)kr0 * HD + kc0);
        cp16(vsD1 + KSTGB, vp + (size_t)kr1 * HD + kc1);
    }
    cp_commit();

    uint32_t kAddr[4], vAddr[4], qAddr;
    {
        int krow = (lane & 15), kcol = (lane >> 4) * 8;
#pragma unroll
        for (int nb = 0; nb < 4; nb++)
            kAddr[nb] = smem_u32(&Ks[nb * 16 + krow][kcol]);
        int vrow = ((lane >> 3) & 1) * 8 + (lane & 7);
        int vcol = ((lane >> 4) & 1) * 8;
#pragma unroll
        for (int nb = 0; nb < 4; nb++)
            vAddr[nb] = smem_u32(&Vs[vrow][vcol + nb * 16]);
        int arow = w * 16 + (lane & 15), acol = (lane >> 4) * 8;
        qAddr = smem_u32(&Qh[arow][acol]);
    }

    uint32_t aqh[4][4];
    float oacc[8][4];
#pragma unroll
    for (int fn = 0; fn < 8; fn++)
#pragma unroll
        for (int r = 0; r < 4; r++) oacc[fn][r] = 0.f;
    float m0 = -1e30f, m1 = -1e30f, l0 = 0.f, l1 = 0.f;

    int r0loc = w * 16 + g;
    int rg0 = qt * QTILE + r0loc;
    int rg1 = rg0 + 8;

    for (int kt = 0; kt < nk; kt++) {
        cp_wait<1>();
        __syncthreads();

        if (kt == 0) {
#pragma unroll
            for (int ks = 0; ks < 4; ks++)
                ldsm_x4(aqh[ks][0], aqh[ks][1], aqh[ks][2], aqh[ks][3], qAddr + ks * 32);
        }

        uint32_t so = (uint32_t)((kt & 1) * KSTGB);

        float s[8][4];
#pragma unroll
        for (int fn = 0; fn < 8; fn++)
#pragma unroll
            for (int r = 0; r < 4; r++) s[fn][r] = 0.f;

#pragma unroll
        for (int ks = 0; ks < 4; ks++) {
            uint32_t kb[8][2];
#pragma unroll
            for (int nb = 0; nb < 4; nb++) {
                uint32_t r0, r1, r2, r3;
                ldsm_x4(r0, r1, r2, r3, kAddr[nb] + so + ks * 32);
                kb[2 * nb][0] = r0; kb[2 * nb + 1][0] = r1;
                kb[2 * nb][1] = r2; kb[2 * nb + 1][1] = r3;
            }
#pragma unroll
            for (int fn = 0; fn < 8; fn++)
                mma_f16(s[fn], aqh[ks][0], aqh[ks][1], aqh[ks][2], aqh[ks][3],
                        kb[fn][0], kb[fn][1]);
        }

        if (kt >= 2 * qt) {
            int cb = kt * KTILE;
#pragma unroll
            for (int fn = 0; fn < 8; fn++) {
                int c = cb + fn * 8 + 2 * tg;
                if (c > rg0)     s[fn][0] = -1e30f;
                if (c + 1 > rg0) s[fn][1] = -1e30f;
                if (c > rg1)     s[fn][2] = -1e30f;
                if (c + 1 > rg1) s[fn][3] = -1e30f;
            }
        }

        float mx0 = -1e30f, mx1 = -1e30f;
#pragma unroll
        for (int fn = 0; fn < 8; fn++) {
            mx0 = fmaxf(mx0, fmaxf(s[fn][0], s[fn][1]));
            mx1 = fmaxf(mx1, fmaxf(s[fn][2], s[fn][3]));
        }
        mx0 = fmaxf(mx0, __shfl_xor_sync(0xffffffffu, mx0, 1));
        mx0 = fmaxf(mx0, __shfl_xor_sync(0xffffffffu, mx0, 2));
        mx1 = fmaxf(mx1, __shfl_xor_sync(0xffffffffu, mx1, 1));
        mx1 = fmaxf(mx1, __shfl_xor_sync(0xffffffffu, mx1, 2));
        float mn0 = fmaxf(m0, mx0), mn1 = fmaxf(m1, mx1);
        float c0 = __expf(m0 - mn0), c1 = __expf(m1 - mn1);
        m0 = mn0; m1 = mn1;

        float su0 = 0.f, su1 = 0.f;
        uint32_t pA[4][4];
#pragma unroll
        for (int fn = 0; fn < 8; fn++) {
            float e0 = __expf(s[fn][0] - mn0);
            float e1 = __expf(s[fn][1] - mn0);
            float e2 = __expf(s[fn][2] - mn1);
            float e3 = __expf(s[fn][3] - mn1);
            su0 += e0 + e1;
            su1 += e2 + e3;
            __half2 p01 = __floats2half2_rn(e0, e1);
            __half2 p23 = __floats2half2_rn(e2, e3);
            int kq = fn >> 1;
            int hi = (fn & 1) * 2;
            pA[kq][hi]     = *(uint32_t*)&p01;
            pA[kq][hi + 1] = *(uint32_t*)&p23;
        }
        su0 += __shfl_xor_sync(0xffffffffu, su0, 1);
        su0 += __shfl_xor_sync(0xffffffffu, su0, 2);
        su1 += __shfl_xor_sync(0xffffffffu, su1, 1);
        su1 += __shfl_xor_sync(0xffffffffu, su1, 2);
        l0 = l0 * c0 + su0;
        l1 = l1 * c1 + su1;

#pragma unroll
        for (int fn = 0; fn < 8; fn++) {
            oacc[fn][0] *= c0; oacc[fn][1] *= c0;
            oacc[fn][2] *= c1; oacc[fn][3] *= c1;
        }

#pragma unroll
        for (int kq = 0; kq < 4; kq++) {
            uint32_t vb[8][2];
#pragma unroll
            for (int nb = 0; nb < 4; nb++) {
                uint32_t r0, r1, r2, r3;
                ldsm_x4t(r0, r1, r2, r3, vAddr[nb] + so + kq * (16 * QST * 2));
                vb[2 * nb][0] = r0; vb[2 * nb][1] = r1;
                vb[2 * nb + 1][0] = r2; vb[2 * nb + 1][1] = r3;
            }
#pragma unroll
            for (int fn = 0; fn < 8; fn++)
                mma_f16(oacc[fn], pA[kq][0], pA[kq][1], pA[kq][2], pA[kq][3],
                        vb[fn][0], vb[fn][1]);
        }

        __syncthreads();   // required: next write targets the stage being read now
        if (kt + 2 < nk) {
            const __half* kp = kbase + (size_t)(kt + 2) * KTILE * HD;
            const __half* vp = vbase + (size_t)(kt + 2) * KTILE * HD;
            uint32_t ds = (uint32_t)((kt & 1) * KSTGB);
            cp16(ksD0 + ds, kp + (size_t)kr0 * HD + kc0);
            cp16(ksD1 + ds, kp + (size_t)kr1 * HD + kc1);
            cp16(vsD0 + ds, vp + (size_t)kr0 * HD + kc0);
            cp16(vsD1 + ds, vp + (size_t)kr1 * HD + kc1);
        }
        cp_commit();
    }

    float inv0 = 1.f / l0, inv1 = 1.f / l1;
    __half* ob = out + (((size_t)b * SEQ + rg0) * NH + h) * HD;
#pragma unroll
    for (int fn = 0; fn < 8; fn++) {
        int c = fn * 8 + 2 * tg;
        __half2 lo = __floats2half2_rn(oacc[fn][0] * inv0, oacc[fn][1] * inv0);
        __half2 hi = __floats2half2_rn(oacc[fn][2] * inv1, oacc[fn][3] * inv1);
        *(__half2*)(ob + c) = lo;
        *(__half2*)(ob + (size_t)8 * NH * HD + c) = hi;
    }
}

// ---------------- launch -----------------------------------------------------
extern "C" void kernel_launch(void* const* d_in, const int* in_sizes, int n_in,
                              void* d_out, int out_size)
{
    const float* x    = (const float*)d_in[0];
    // d_in[1] = mask (causal) — analytic
    const float* cosp = (const float*)d_in[2];
    const float* sinp = (const float*)d_in[3];
    const float* Wq   = (const float*)d_in[4];
    const float* Wk   = (const float*)d_in[5];
    const float* Wv   = (const float*)d_in[6];
    const float* Wo   = (const float*)d_in[7];

    float* out    = (float*)d_out;
    float* next_k = out + (size_t)Bsz * SEQ * EMB;
    float* next_v = next_k + (size_t)Bsz * NKV * SEQ * HD;

    __half *xh, *wqh, *wkh, *wvh, *woh, *qh, *kh, *vh, *ah;
    cudaGetSymbolAddress((void**)&xh,  g_xh);
    cudaGetSymbolAddress((void**)&wqh, g_wqh);
    cudaGetSymbolAddress((void**)&wkh, g_wkh);
    cudaGetSymbolAddress((void**)&wvh, g_wvh);
    cudaGetSymbolAddress((void**)&woh, g_woh);
    cudaGetSymbolAddress((void**)&qh,  g_qh);
    cudaGetSymbolAddress((void**)&kh,  g_kh);
    cudaGetSymbolAddress((void**)&vh,  g_vh);
    cudaGetSymbolAddress((void**)&ah,  g_ah);

    static bool cfg = false;
    if (!cfg) {
        cudaFuncSetAttribute(attn_h16, cudaFuncAttributeMaxDynamicSharedMemorySize,
                             ATTN_SMEM);
        cfg = true;
    }

    // fp32 -> fp16 conversions (single segmented launch)
    cvt5<<<dim3(1024, 5), 256>>>(x, xh, BSxS * EMB,
                                 Wq, wqh, EMB * EMB,
                                 Wk, wkh, EMB * NKV * HD,
                                 Wv, wvh, EMB * NKV * HD,
                                 Wo, woh, EMB * EMB);

    // Q projection with fused RoPE+scale -> fp16 qh
    h16_gemm<1><<<dim3(EMB / TN, BSxS / TM, 1), 256>>>(
        xh, wqh, wqh, nullptr, nullptr, qh, nullptr, cosp, sinp, BSxS, EMB, EMB);
    // K/V projections with fused RoPE(K)/transpose -> next_k/next_v fp32 + kh/vh fp16
    h16_gemm<2><<<dim3((NKV * HD) / TN, BSxS / TM, 2), 256>>>(
        xh, wkh, wvh, next_k, next_v, kh, vh, cosp, sinp, BSxS, NKV * HD, EMB);

    // Flash attention
    attn_h16<<<dim3(SEQ / QTILE, NH, Bsz), 256, ATTN_SMEM>>>(qh, kh, vh, ah);

    // Output projection (plain fp32 epilogue)
    h16_gemm<0><<<dim3(EMB / TN, BSxS / TM, 1), 256>>>(
        ah, woh, woh, out, nullptr, nullptr, nullptr, nullptr, nullptr,
        BSxS, EMB, EMB);
}

// round 9
// speedup vs baseline: 1.5039x; 1.5039x over previous
#include <cuda_runtime.h>
#include <cuda_fp16.h>
#include <cstdint>

// Problem constants
#define Bsz 2
#define SEQ 2048
#define EMB 2048
#define NH  32
#define NKV 8
#define HD  64
#define BSxS (Bsz*SEQ) // 4096

// ---------------- scratch ----------------------------------------------------
__device__ __half g_xh[(size_t)BSxS * EMB];           // x fp16
__device__ __half g_wqh[(size_t)EMB * EMB];
__device__ __half g_wkh[(size_t)EMB * NKV * HD];
__device__ __half g_wvh[(size_t)EMB * NKV * HD];
__device__ __half g_woh[(size_t)EMB * EMB];
__device__ __half g_qh[(size_t)BSxS * EMB];           // roped+scaled Q fp16 (B,S,H,D)
__device__ __half g_kh[(size_t)Bsz * NKV * SEQ * HD]; // roped K fp16 (B,KV,S,D)
__device__ __half g_vh[(size_t)Bsz * NKV * SEQ * HD]; // V fp16 (B,KV,S,D)
__device__ __half g_ah[(size_t)BSxS * EMB];           // attention out fp16

// ---------------- PTX helpers ------------------------------------------------
__device__ __forceinline__ uint32_t smem_u32(const void* p) {
    return (uint32_t)__cvta_generic_to_shared(p);
}
__device__ __forceinline__ void ldsm_x4(uint32_t& r0, uint32_t& r1, uint32_t& r2,
                                        uint32_t& r3, uint32_t addr) {
    asm volatile("ldmatrix.sync.aligned.m8n8.x4.shared.b16 {%0,%1,%2,%3},[%4];"
                 : "=r"(r0), "=r"(r1), "=r"(r2), "=r"(r3) : "r"(addr));
}
__device__ __forceinline__ void ldsm_x4t(uint32_t& r0, uint32_t& r1, uint32_t& r2,
                                         uint32_t& r3, uint32_t addr) {
    asm volatile("ldmatrix.sync.aligned.m8n8.x4.trans.shared.b16 {%0,%1,%2,%3},[%4];"
                 : "=r"(r0), "=r"(r1), "=r"(r2), "=r"(r3) : "r"(addr));
}
__device__ __forceinline__ void mma_f16(float c[4], uint32_t a0, uint32_t a1,
                                        uint32_t a2, uint32_t a3,
                                        uint32_t b0, uint32_t b1) {
    asm volatile(
        "mma.sync.aligned.m16n8k16.row.col.f32.f16.f16.f32 "
        "{%0,%1,%2,%3},{%4,%5,%6,%7},{%8,%9},{%0,%1,%2,%3};"
        : "+f"(c[0]), "+f"(c[1]), "+f"(c[2]), "+f"(c[3])
        : "r"(a0), "r"(a1), "r"(a2), "r"(a3), "r"(b0), "r"(b1));
}
__device__ __forceinline__ void st_half4(__half* p, float4 v) {
    __half2 h0 = __floats2half2_rn(v.x, v.y);
    __half2 h1 = __floats2half2_rn(v.z, v.w);
    uint2 u;
    u.x = *(uint32_t*)&h0;
    u.y = *(uint32_t*)&h1;
    *(uint2*)p = u;
}
__device__ __forceinline__ void cp16(uint32_t dst, const void* src) {
    asm volatile("cp.async.ca.shared.global [%0], [%1], 16;" :: "r"(dst), "l"(src));
}
__device__ __forceinline__ void cp_commit() {
    asm volatile("cp.async.commit_group;" ::: "memory");
}
template <int N>
__device__ __forceinline__ void cp_wait() {
    asm volatile("cp.async.wait_group %0;" :: "n"(N) : "memory");
}

// ---------------- merged fp32 -> fp16 conversions (5 segments) ---------------
__global__ void cvt5(const float* s0, __half* d0, int n0,
                     const float* s1, __half* d1, int n1,
                     const float* s2, __half* d2, int n2,
                     const float* s3, __half* d3, int n3,
                     const float* s4, __half* d4, int n4)
{
    const float* s; __half* d; int n;
    switch (blockIdx.y) {
        case 0: s = s0; d = d0; n = n0; break;
        case 1: s = s1; d = d1; n = n1; break;
        case 2: s = s2; d = d2; n = n2; break;
        case 3: s = s3; d = d3; n = n3; break;
        default: s = s4; d = d4; n = n4; break;
    }
    int stride = gridDim.x * blockDim.x * 4;
    for (int i = (blockIdx.x * blockDim.x + threadIdx.x) * 4; i < n; i += stride)
        st_half4(d + i, *(const float4*)(s + i));
}

// ---------------- fp16 cp.async pipelined GEMM with fused epilogues ----------
// MODE 0: plain fp32 C0.
// MODE 1: RoPE+1/8 scale -> fp16 H0 (Q projection; warp n-tile = 1 head)
// MODE 2: z=0: RoPE + transpose -> fp32 C0 + fp16 H0 (K); z=1: transpose -> C1/H1 (V)
#define TM 128
#define TN 128
#define TK 32
#define AST 40
#define BST 136
#define STG 3
#define ASZ (TM * AST * 2)
#define BSZ (TK * BST * 2)

template <int MODE>
__global__ __launch_bounds__(256, 2) void h16_gemm(   // cap regs at 128 -> 2 CTAs/SM
    const __half* __restrict__ A,
    const __half* __restrict__ B0, const __half* __restrict__ B1,
    float* __restrict__ C0, float* __restrict__ C1,
    __half* __restrict__ H0, __half* __restrict__ H1,
    const float* __restrict__ cosp, const float* __restrict__ sinp,
    int M, int N, int K)
{
    __shared__ __align__(16) __half As[STG][TM][AST];
    __shared__ __align__(16) __half Bs[STG][TK][BST];

    const __half* B = (blockIdx.z == 0) ? B0 : B1;

    int tid = threadIdx.x, lane = tid & 31, wid = tid >> 5;
    int wm = wid & 3, wn = wid >> 2;
    int g = lane >> 2, tg = lane & 3;

    const __half* Ab = A + (size_t)blockIdx.y * TM * K;
    const __half* Bb = B + (size_t)blockIdx.x * TN;

    float acc[2][8][4];
#pragma unroll
    for (int i = 0; i < 2; i++)
#pragma unroll
        for (int j = 0; j < 8; j++)
#pragma unroll
            for (int r = 0; r < 4; r++) acc[i][j][r] = 0.f;

    int ar0 = tid >> 2, ac0 = (tid & 3) * 8;
    int ar1 = (tid + 256) >> 2, ac1 = ((tid + 256) & 3) * 8;
    int br0 = tid >> 4, bc0 = (tid & 15) * 8;
    int br1 = (tid + 256) >> 4, bc1 = ((tid + 256) & 15) * 8;
    uint32_t aD0 = smem_u32(&As[0][ar0][ac0]);
    uint32_t aD1 = smem_u32(&As[0][ar1][ac1]);
    uint32_t bD0 = smem_u32(&Bs[0][br0][bc0]);
    uint32_t bD1 = smem_u32(&Bs[0][br1][bc1]);

    uint32_t aAddr[2], bAddr[4];
    {
        int arow = wm * 32 + (lane & 15);
        int acol = (lane >> 4) * 8;
        aAddr[0] = smem_u32(&As[0][arow][acol]);
        aAddr[1] = smem_u32(&As[0][arow + 16][acol]);
        int brow = ((lane >> 3) & 1) * 8 + (lane & 7);
        int bcol = wn * 64 + ((lane >> 4) & 1) * 8;
#pragma unroll
        for (int nb = 0; nb < 4; nb++)
            bAddr[nb] = smem_u32(&Bs[0][brow][bcol + nb * 16]);
    }

    int nt = K / TK;

#pragma unroll
    for (int p = 0; p < 2; p++) {
        int k0 = p * TK;
        cp16(aD0 + p * ASZ, Ab + (size_t)ar0 * K + k0 + ac0);
        cp16(aD1 + p * ASZ, Ab + (size_t)ar1 * K + k0 + ac1);
        cp16(bD0 + p * BSZ, Bb + (size_t)(k0 + br0) * N + bc0);
        cp16(bD1 + p * BSZ, Bb + (size_t)(k0 + br1) * N + bc1);
        cp_commit();
    }

    int st = 0;
    for (int t = 0; t < nt; t++) {
        cp_wait<1>();
        __syncthreads();

        uint32_t aOff = (uint32_t)(st * ASZ);
        uint32_t bOff = (uint32_t)(st * BSZ);
#pragma unroll
        for (int ks = 0; ks < 2; ks++) {
            uint32_t af[2][4];
            ldsm_x4(af[0][0], af[0][1], af[0][2], af[0][3], aAddr[0] + aOff + ks * 32);
            ldsm_x4(af[1][0], af[1][1], af[1][2], af[1][3], aAddr[1] + aOff + ks * 32);
            uint32_t bf[8][2];
#pragma unroll
            for (int nb = 0; nb < 4; nb++) {
                uint32_t r0, r1, r2, r3;
                ldsm_x4t(r0, r1, r2, r3, bAddr[nb] + bOff + ks * (16 * BST * 2));
                bf[2 * nb][0] = r0; bf[2 * nb][1] = r1;
                bf[2 * nb + 1][0] = r2; bf[2 * nb + 1][1] = r3;
            }
#pragma unroll
            for (int mf = 0; mf < 2; mf++)
#pragma unroll
                for (int fn = 0; fn < 8; fn++)
                    mma_f16(acc[mf][fn], af[mf][0], af[mf][1], af[mf][2], af[mf][3],
                            bf[fn][0], bf[fn][1]);
        }
        __syncthreads();   // phase separation (R7-proven structure)

        if (t + 2 < nt) {
            int ns = (st + 2) % STG;
            int k0 = (t + 2) * TK;
            cp16(aD0 + ns * ASZ, Ab + (size_t)ar0 * K + k0 + ac0);
            cp16(aD1 + ns * ASZ, Ab + (size_t)ar1 * K + k0 + ac1);
            cp16(bD0 + ns * BSZ, Bb + (size_t)(k0 + br0) * N + bc0);
            cp16(bD1 + ns * BSZ, Bb + (size_t)(k0 + br1) * N + bc1);
        }
        cp_commit();
        st = (st + 1) % STG;
    }

    // ---------------- epilogues ----------------
    if (MODE == 0) {
#pragma unroll
        for (int mf = 0; mf < 2; mf++) {
            int row0 = blockIdx.y * TM + wm * 32 + mf * 16 + g;
#pragma unroll
            for (int fn = 0; fn < 8; fn++) {
                int col = blockIdx.x * TN + wn * 64 + fn * 8 + tg * 2;
                *(float2*)&C0[(size_t)row0 * N + col] =
                    make_float2(acc[mf][fn][0], acc[mf][fn][1]);
                *(float2*)&C0[(size_t)(row0 + 8) * N + col] =
                    make_float2(acc[mf][fn][2], acc[mf][fn][3]);
            }
        }
    } else if (MODE == 1) {
        // Q: RoPE + 1/8 scale, fp16 out. Pairs: acc[][fn] (d) with acc[][fn+4] (d+32).
        int colb = blockIdx.x * TN + wn * 64;
#pragma unroll
        for (int mf = 0; mf < 2; mf++) {
            int row0 = blockIdx.y * TM + wm * 32 + mf * 16 + g;
            int sA = row0 & (SEQ - 1);
            int sB = sA + 8;
#pragma unroll
            for (int fn = 0; fn < 4; fn++) {
                int d0 = fn * 8 + tg * 2;
                float2 cA = *(const float2*)&cosp[sA * HD + d0];
                float2 nA = *(const float2*)&sinp[sA * HD + d0];
                float2 cB = *(const float2*)&cosp[sB * HD + d0];
                float2 nB = *(const float2*)&sinp[sB * HD + d0];
                float x10 = acc[mf][fn][0], x11 = acc[mf][fn][1];
                float x20 = acc[mf][fn + 4][0], x21 = acc[mf][fn + 4][1];
                __half2 lo = __floats2half2_rn((x10 * cA.x - x20 * nA.x) * 0.125f,
                                               (x11 * cA.y - x21 * nA.y) * 0.125f);
                __half2 hi = __floats2half2_rn((x20 * cA.x + x10 * nA.x) * 0.125f,
                                               (x21 * cA.y + x11 * nA.y) * 0.125f);
                *(__half2*)&H0[(size_t)row0 * N + colb + d0]      = lo;
                *(__half2*)&H0[(size_t)row0 * N + colb + d0 + 32] = hi;
                x10 = acc[mf][fn][2]; x11 = acc[mf][fn][3];
                x20 = acc[mf][fn + 4][2]; x21 = acc[mf][fn + 4][3];
                lo = __floats2half2_rn((x10 * cB.x - x20 * nB.x) * 0.125f,
                                       (x11 * cB.y - x21 * nB.y) * 0.125f);
                hi = __floats2half2_rn((x20 * cB.x + x10 * nB.x) * 0.125f,
                                       (x21 * cB.y + x11 * nB.y) * 0.125f);
                *(__half2*)&H0[(size_t)(row0 + 8) * N + colb + d0]      = lo;
                *(__half2*)&H0[(size_t)(row0 + 8) * N + colb + d0 + 32] = hi;
            }
        }
    } else {
        // KV: transpose (B,S,KV,D)->(B,KV,S,D); z=0 rope (K), z=1 plain (V).
        float* Cz  = (blockIdx.z == 0) ? C0 : C1;
        __half* Hz = (blockIdx.z == 0) ? H0 : H1;
        bool dorope = (blockIdx.z == 0);
        int colb = blockIdx.x * TN + wn * 64;
        int kvh = colb >> 6;
#pragma unroll
        for (int mf = 0; mf < 2; mf++) {
            int row0 = blockIdx.y * TM + wm * 32 + mf * 16 + g;
            int sA = row0 & (SEQ - 1);
            int bA = row0 >> 11;
            size_t oA = (((size_t)bA * NKV + kvh) * SEQ + sA) * HD;
            size_t oB = oA + (size_t)8 * HD;
#pragma unroll
            for (int fn = 0; fn < 4; fn++) {
                int d0 = fn * 8 + tg * 2;
                float r0, r1, r2, r3, q0, q1, q2, q3;
                if (dorope) {
                    float2 cA = *(const float2*)&cosp[sA * HD + d0];
                    float2 nA = *(const float2*)&sinp[sA * HD + d0];
                    float2 cB = *(const float2*)&cosp[(sA + 8) * HD + d0];
                    float2 nB = *(const float2*)&sinp[(sA + 8) * HD + d0];
                    r0 = acc[mf][fn][0] * cA.x - acc[mf][fn + 4][0] * nA.x;
                    r1 = acc[mf][fn][1] * cA.y - acc[mf][fn + 4][1] * nA.y;
                    r2 = acc[mf][fn + 4][0] * cA.x + acc[mf][fn][0] * nA.x;
                    r3 = acc[mf][fn + 4][1] * cA.y + acc[mf][fn][1] * nA.y;
                    q0 = acc[mf][fn][2] * cB.x - acc[mf][fn + 4][2] * nB.x;
                    q1 = acc[mf][fn][3] * cB.y - acc[mf][fn + 4][3] * nB.y;
                    q2 = acc[mf][fn + 4][2] * cB.x + acc[mf][fn][2] * nB.x;
                    q3 = acc[mf][fn + 4][3] * cB.y + acc[mf][fn][3] * nB.y;
                } else {
                    r0 = acc[mf][fn][0]; r1 = acc[mf][fn][1];
                    r2 = acc[mf][fn + 4][0]; r3 = acc[mf][fn + 4][1];
                    q0 = acc[mf][fn][2]; q1 = acc[mf][fn][3];
                    q2 = acc[mf][fn + 4][2]; q3 = acc[mf][fn + 4][3];
                }
                *(float2*)&Cz[oA + d0]      = make_float2(r0, r1);
                *(float2*)&Cz[oA + d0 + 32] = make_float2(r2, r3);
                *(float2*)&Cz[oB + d0]      = make_float2(q0, q1);
                *(float2*)&Cz[oB + d0 + 32] = make_float2(q2, q3);
                *(__half2*)&Hz[oA + d0]      = __floats2half2_rn(r0, r1);
                *(__half2*)&Hz[oA + d0 + 32] = __floats2half2_rn(r2, r3);
                *(__half2*)&Hz[oB + d0]      = __floats2half2_rn(q0, q1);
                *(__half2*)&Hz[oB + d0 + 32] = __floats2half2_rn(q2, q3);
            }
        }
    }
}

// ---------------- Tensor-core flash attention (causal) -----------------------
// grid (S/128, NH, B), 256 threads. Longest blocks (high qt) launch first.
#define QTILE 128
#define KTILE 64
#define QST 72
#define KSTGB (KTILE * QST * 2)
#define ATTN_SMEM ((QTILE + 4 * KTILE) * QST * 2)  // 55296 B

__global__ __launch_bounds__(256) void attn_h16(
    const __half* __restrict__ q,
    const __half* __restrict__ kk,
    const __half* __restrict__ vv,
    __half* __restrict__ out)
{
    extern __shared__ __align__(16) __half sm[];
    __half (*Qh)[QST] = (__half(*)[QST])sm;
    __half (*Ks)[QST] = (__half(*)[QST])(sm + QTILE * QST);
    __half (*Vs)[QST] = (__half(*)[QST])(sm + (QTILE + 2 * KTILE) * QST);

    int qt = gridDim.x - 1 - blockIdx.x;   // longest work first
    int h = blockIdx.y, b = blockIdx.z;
    int kv = h >> 2;
    int tid = threadIdx.x, lane = tid & 31, w = tid >> 5;
    int g = lane >> 2, tg = lane & 3;

    const __half* qbase = q + (((size_t)b * SEQ + (size_t)qt * QTILE) * NH + h) * HD;
    const __half* kbase = kk + ((size_t)b * NKV + kv) * SEQ * HD;
    const __half* vbase = vv + ((size_t)b * NKV + kv) * SEQ * HD;

    int kr0 = tid >> 3, kc0 = (tid & 7) * 8;
    int kr1 = (tid + 256) >> 3, kc1 = ((tid + 256) & 7) * 8;
    uint32_t ksD0 = smem_u32(&Ks[kr0][kc0]), ksD1 = smem_u32(&Ks[kr1][kc1]);
    uint32_t vsD0 = smem_u32(&Vs[kr0][kc0]), vsD1 = smem_u32(&Vs[kr1][kc1]);

    int nk = 2 * qt + 2;

#pragma unroll
    for (int i = 0; i < 4; i++) {
        int c = tid + i * 256;
        int r = c >> 3, col = (c & 7) * 8;
        cp16(smem_u32(&Qh[r][col]), qbase + (size_t)r * NH * HD + col);
    }
    {
        cp16(ksD0, kbase + (size_t)kr0 * HD + kc0);
        cp16(ksD1, kbase + (size_t)kr1 * HD + kc1);
        cp16(vsD0, vbase + (size_t)kr0 * HD + kc0);
        cp16(vsD1, vbase + (size_t)kr1 * HD + kc1);
    }
    cp_commit();
    {
        const __half* kp = kbase + (size_t)KTILE * HD;
        const __half* vp = vbase + (size_t)KTILE * HD;
        cp16(ksD0 + KSTGB, kp + (size_t)kr0 * HD + kc0);
        cp16(ksD1 + KSTGB, kp + (size_t)kr1 * HD + kc1);
        cp16(vsD0 + KSTGB, vp + (size_t)kr0 * HD + kc0);
        cp16(vsD1 + KSTGB, vp + (size_t)kr1 * HD + kc1);
    }
    cp_commit();

    uint32_t kAddr[4], vAddr[4], qAddr;
    {
        int krow = (lane & 15), kcol = (lane >> 4) * 8;
#pragma unroll
        for (int nb = 0; nb < 4; nb++)
            kAddr[nb] = smem_u32(&Ks[nb * 16 + krow][kcol]);
        int vrow = ((lane >> 3) & 1) * 8 + (lane & 7);
        int vcol = ((lane >> 4) & 1) * 8;
#pragma unroll
        for (int nb = 0; nb < 4; nb++)
            vAddr[nb] = smem_u32(&Vs[vrow][vcol + nb * 16]);
        int arow = w * 16 + (lane & 15), acol = (lane >> 4) * 8;
        qAddr = smem_u32(&Qh[arow][acol]);
    }

    uint32_t aqh[4][4];
    float oacc[8][4];
#pragma unroll
    for (int fn = 0; fn < 8; fn++)
#pragma unroll
        for (int r = 0; r < 4; r++) oacc[fn][r] = 0.f;
    float m0 = -1e30f, m1 = -1e30f, l0 = 0.f, l1 = 0.f;

    int r0loc = w * 16 + g;
    int rg0 = qt * QTILE + r0loc;
    int rg1 = rg0 + 8;

    for (int kt = 0; kt < nk; kt++) {
        cp_wait<1>();
        __syncthreads();

        if (kt == 0) {
#pragma unroll
            for (int ks = 0; ks < 4; ks++)
                ldsm_x4(aqh[ks][0], aqh[ks][1], aqh[ks][2], aqh[ks][3], qAddr + ks * 32);
        }

        uint32_t so = (uint32_t)((kt & 1) * KSTGB);

        float s[8][4];
#pragma unroll
        for (int fn = 0; fn < 8; fn++)
#pragma unroll
            for (int r = 0; r < 4; r++) s[fn][r] = 0.f;

#pragma unroll
        for (int ks = 0; ks < 4; ks++) {
            uint32_t kb[8][2];
#pragma unroll
            for (int nb = 0; nb < 4; nb++) {
                uint32_t r0, r1, r2, r3;
                ldsm_x4(r0, r1, r2, r3, kAddr[nb] + so + ks * 32);
                kb[2 * nb][0] = r0; kb[2 * nb + 1][0] = r1;
                kb[2 * nb][1] = r2; kb[2 * nb + 1][1] = r3;
            }
#pragma unroll
            for (int fn = 0; fn < 8; fn++)
                mma_f16(s[fn], aqh[ks][0], aqh[ks][1], aqh[ks][2], aqh[ks][3],
                        kb[fn][0], kb[fn][1]);
        }

        if (kt >= 2 * qt) {
            int cb = kt * KTILE;
#pragma unroll
            for (int fn = 0; fn < 8; fn++) {
                int c = cb + fn * 8 + 2 * tg;
                if (c > rg0)     s[fn][0] = -1e30f;
                if (c + 1 > rg0) s[fn][1] = -1e30f;
                if (c > rg1)     s[fn][2] = -1e30f;
                if (c + 1 > rg1) s[fn][3] = -1e30f;
            }
        }

        float mx0 = -1e30f, mx1 = -1e30f;
#pragma unroll
        for (int fn = 0; fn < 8; fn++) {
            mx0 = fmaxf(mx0, fmaxf(s[fn][0], s[fn][1]));
            mx1 = fmaxf(mx1, fmaxf(s[fn][2], s[fn][3]));
        }
        mx0 = fmaxf(mx0, __shfl_xor_sync(0xffffffffu, mx0, 1));
        mx0 = fmaxf(mx0, __shfl_xor_sync(0xffffffffu, mx0, 2));
        mx1 = fmaxf(mx1, __shfl_xor_sync(0xffffffffu, mx1, 1));
        mx1 = fmaxf(mx1, __shfl_xor_sync(0xffffffffu, mx1, 2));
        float mn0 = fmaxf(m0, mx0), mn1 = fmaxf(m1, mx1);
        float c0 = __expf(m0 - mn0), c1 = __expf(m1 - mn1);
        m0 = mn0; m1 = mn1;

        float su0 = 0.f, su1 = 0.f;
        uint32_t pA[4][4];
#pragma unroll
        for (int fn = 0; fn < 8; fn++) {
            float e0 = __expf(s[fn][0] - mn0);
            float e1 = __expf(s[fn][1] - mn0);
            float e2 = __expf(s[fn][2] - mn1);
            float e3 = __expf(s[fn][3] - mn1);
            su0 += e0 + e1;
            su1 += e2 + e3;
            __half2 p01 = __floats2half2_rn(e0, e1);
            __half2 p23 = __floats2half2_rn(e2, e3);
            int kq = fn >> 1;
            int hi = (fn & 1) * 2;
            pA[kq][hi]     = *(uint32_t*)&p01;
            pA[kq][hi + 1] = *(uint32_t*)&p23;
        }
        su0 += __shfl_xor_sync(0xffffffffu, su0, 1);
        su0 += __shfl_xor_sync(0xffffffffu, su0, 2);
        su1 += __shfl_xor_sync(0xffffffffu, su1, 1);
        su1 += __shfl_xor_sync(0xffffffffu, su1, 2);
        l0 = l0 * c0 + su0;
        l1 = l1 * c1 + su1;

#pragma unroll
        for (int fn = 0; fn < 8; fn++) {
            oacc[fn][0] *= c0; oacc[fn][1] *= c0;
            oacc[fn][2] *= c1; oacc[fn][3] *= c1;
        }

#pragma unroll
        for (int kq = 0; kq < 4; kq++) {
            uint32_t vb[8][2];
#pragma unroll
            for (int nb = 0; nb < 4; nb++) {
                uint32_t r0, r1, r2, r3;
                ldsm_x4t(r0, r1, r2, r3, vAddr[nb] + so + kq * (16 * QST * 2));
                vb[2 * nb][0] = r0; vb[2 * nb][1] = r1;
                vb[2 * nb + 1][0] = r2; vb[2 * nb + 1][1] = r3;
            }
#pragma unroll
            for (int fn = 0; fn < 8; fn++)
                mma_f16(oacc[fn], pA[kq][0], pA[kq][1], pA[kq][2], pA[kq][3],
                        vb[fn][0], vb[fn][1]);
        }

        __syncthreads();
        if (kt + 2 < nk) {
            const __half* kp = kbase + (size_t)(kt + 2) * KTILE * HD;
            const __half* vp = vbase + (size_t)(kt + 2) * KTILE * HD;
            uint32_t ds = (uint32_t)((kt & 1) * KSTGB);
            cp16(ksD0 + ds, kp + (size_t)kr0 * HD + kc0);
            cp16(ksD1 + ds, kp + (size_t)kr1 * HD + kc1);
            cp16(vsD0 + ds, vp + (size_t)kr0 * HD + kc0);
            cp16(vsD1 + ds, vp + (size_t)kr1 * HD + kc1);
        }
        cp_commit();
    }

    float inv0 = 1.f / l0, inv1 = 1.f / l1;
    __half* ob = out + (((size_t)b * SEQ + rg0) * NH + h) * HD;
#pragma unroll
    for (int fn = 0; fn < 8; fn++) {
        int c = fn * 8 + 2 * tg;
        __half2 lo = __floats2half2_rn(oacc[fn][0] * inv0, oacc[fn][1] * inv0);
        __half2 hi = __floats2half2_rn(oacc[fn][2] * inv1, oacc[fn][3] * inv1);
        *(__half2*)(ob + c) = lo;
        *(__half2*)(ob + (size_t)8 * NH * HD + c) = hi;
    }
}

// ---------------- launch -----------------------------------------------------
extern "C" void kernel_launch(void* const* d_in, const int* in_sizes, int n_in,
                              void* d_out, int out_size)
{
    const float* x    = (const float*)d_in[0];
    // d_in[1] = mask (causal) — analytic
    const float* cosp = (const float*)d_in[2];
    const float* sinp = (const float*)d_in[3];
    const float* Wq   = (const float*)d_in[4];
    const float* Wk   = (const float*)d_in[5];
    const float* Wv   = (const float*)d_in[6];
    const float* Wo   = (const float*)d_in[7];

    float* out    = (float*)d_out;
    float* next_k = out + (size_t)Bsz * SEQ * EMB;
    float* next_v = next_k + (size_t)Bsz * NKV * SEQ * HD;

    __half *xh, *wqh, *wkh, *wvh, *woh, *qh, *kh, *vh, *ah;
    cudaGetSymbolAddress((void**)&xh,  g_xh);
    cudaGetSymbolAddress((void**)&wqh, g_wqh);
    cudaGetSymbolAddress((void**)&wkh, g_wkh);
    cudaGetSymbolAddress((void**)&wvh, g_wvh);
    cudaGetSymbolAddress((void**)&woh, g_woh);
    cudaGetSymbolAddress((void**)&qh,  g_qh);
    cudaGetSymbolAddress((void**)&kh,  g_kh);
    cudaGetSymbolAddress((void**)&vh,  g_vh);
    cudaGetSymbolAddress((void**)&ah,  g_ah);

    static bool cfg = false;
    if (!cfg) {
        cudaFuncSetAttribute(attn_h16, cudaFuncAttributeMaxDynamicSharedMemorySize,
                             ATTN_SMEM);
        cfg = true;
    }

    // fp32 -> fp16 conversions (single segmented launch)
    cvt5<<<dim3(1024, 5), 256>>>(x, xh, BSxS * EMB,
                                 Wq, wqh, EMB * EMB,
                                 Wk, wkh, EMB * NKV * HD,
                                 Wv, wvh, EMB * NKV * HD,
                                 Wo, woh, EMB * EMB);

    // Q projection with fused RoPE+scale -> fp16 qh
    h16_gemm<1><<<dim3(EMB / TN, BSxS / TM, 1), 256>>>(
        xh, wqh, wqh, nullptr, nullptr, qh, nullptr, cosp, sinp, BSxS, EMB, EMB);
    // K/V projections with fused RoPE(K)/transpose -> next_k/next_v fp32 + kh/vh fp16
    h16_gemm<2><<<dim3((NKV * HD) / TN, BSxS / TM, 2), 256>>>(
        xh, wkh, wvh, next_k, next_v, kh, vh, cosp, sinp, BSxS, NKV * HD, EMB);

    // Flash attention
    attn_h16<<<dim3(SEQ / QTILE, NH, Bsz), 256, ATTN_SMEM>>>(qh, kh, vh, ah);

    // Output projection (plain fp32 epilogue)
    h16_gemm<0><<<dim3(EMB / TN, BSxS / TM, 1), 256>>>(
        ah, woh, woh, out, nullptr, nullptr, nullptr, nullptr, nullptr,
        BSxS, EMB, EMB);
}

// round 13
// speedup vs baseline: 1.5620x; 1.0386x over previous
#include <cuda_runtime.h>
#include <cuda_fp16.h>
#include <cstdint>

// Problem constants
#define Bsz 2
#define SEQ 2048
#define EMB 2048
#define NH  32
#define NKV 8
#define HD  64
#define BSxS (Bsz*SEQ) // 4096

// Q scale with log2(e) folded in (softmax computed base-2)
#define QSCALE 0.1803368801111204f   // 0.125 * log2(e)

// ---------------- scratch ----------------------------------------------------
__device__ __half g_xh[(size_t)BSxS * EMB];           // x fp16
__device__ __half g_wqh[(size_t)EMB * EMB];
__device__ __half g_wkh[(size_t)EMB * NKV * HD];
__device__ __half g_wvh[(size_t)EMB * NKV * HD];
__device__ __half g_woh[(size_t)EMB * EMB];
__device__ __half g_qh[(size_t)BSxS * EMB];           // roped+scaled Q fp16 (B,S,H,D)
__device__ __half g_kh[(size_t)Bsz * NKV * SEQ * HD]; // roped K fp16 (B,KV,S,D)
__device__ __half g_vh[(size_t)Bsz * NKV * SEQ * HD]; // V fp16 (B,KV,S,D)
__device__ __half g_ah[(size_t)BSxS * EMB];           // attention out fp16

// ---------------- PTX helpers ------------------------------------------------
__device__ __forceinline__ uint32_t smem_u32(const void* p) {
    return (uint32_t)__cvta_generic_to_shared(p);
}
__device__ __forceinline__ void ldsm_x4(uint32_t& r0, uint32_t& r1, uint32_t& r2,
                                        uint32_t& r3, uint32_t addr) {
    asm volatile("ldmatrix.sync.aligned.m8n8.x4.shared.b16 {%0,%1,%2,%3},[%4];"
                 : "=r"(r0), "=r"(r1), "=r"(r2), "=r"(r3) : "r"(addr));
}
__device__ __forceinline__ void ldsm_x4t(uint32_t& r0, uint32_t& r1, uint32_t& r2,
                                         uint32_t& r3, uint32_t addr) {
    asm volatile("ldmatrix.sync.aligned.m8n8.x4.trans.shared.b16 {%0,%1,%2,%3},[%4];"
                 : "=r"(r0), "=r"(r1), "=r"(r2), "=r"(r3) : "r"(addr));
}
__device__ __forceinline__ void mma_f16(float c[4], uint32_t a0, uint32_t a1,
                                        uint32_t a2, uint32_t a3,
                                        uint32_t b0, uint32_t b1) {
    asm volatile(
        "mma.sync.aligned.m16n8k16.row.col.f32.f16.f16.f32 "
        "{%0,%1,%2,%3},{%4,%5,%6,%7},{%8,%9},{%0,%1,%2,%3};"
        : "+f"(c[0]), "+f"(c[1]), "+f"(c[2]), "+f"(c[3])
        : "r"(a0), "r"(a1), "r"(a2), "r"(a3), "r"(b0), "r"(b1));
}
__device__ __forceinline__ void st_half4(__half* p, float4 v) {
    __half2 h0 = __floats2half2_rn(v.x, v.y);
    __half2 h1 = __floats2half2_rn(v.z, v.w);
    uint2 u;
    u.x = *(uint32_t*)&h0;
    u.y = *(uint32_t*)&h1;
    *(uint2*)p = u;
}
__device__ __forceinline__ void cp16(uint32_t dst, const void* src) {
    asm volatile("cp.async.ca.shared.global [%0], [%1], 16;" :: "r"(dst), "l"(src));
}
__device__ __forceinline__ void cp_commit() {
    asm volatile("cp.async.commit_group;" ::: "memory");
}
template <int N>
__device__ __forceinline__ void cp_wait() {
    asm volatile("cp.async.wait_group %0;" :: "n"(N) : "memory");
}

// ---------------- merged fp32 -> fp16 conversions (5 segments) ---------------
__global__ void cvt5(const float* s0, __half* d0, int n0,
                     const float* s1, __half* d1, int n1,
                     const float* s2, __half* d2, int n2,
                     const float* s3, __half* d3, int n3,
                     const float* s4, __half* d4, int n4)
{
    const float* s; __half* d; int n;
    switch (blockIdx.y) {
        case 0: s = s0; d = d0; n = n0; break;
        case 1: s = s1; d = d1; n = n1; break;
        case 2: s = s2; d = d2; n = n2; break;
        case 3: s = s3; d = d3; n = n3; break;
        default: s = s4; d = d4; n = n4; break;
    }
    int stride = gridDim.x * blockDim.x * 4;
    for (int i = (blockIdx.x * blockDim.x + threadIdx.x) * 4; i < n; i += stride)
        st_half4(d + i, *(const float4*)(s + i));
}

// ---------------- fp16 cp.async pipelined GEMM with fused epilogues ----------
// MODE 0: plain fp32 Cout (Wo projection), grid (16, 32).
// MODE 3: fused QKV projection, grid (24, 32):
//   bx  0..15 -> x@Wq, RoPE+QSCALE -> fp16 Hq
//   bx 16..19 -> x@Wk, RoPE + transpose -> fp32 nK + fp16 Hk
//   bx 20..23 -> x@Wv, transpose -> fp32 nV + fp16 Hv
#define TM 128
#define TN 128
#define TK 32
#define AST 40
#define BST 136
#define STG 3
#define ASZ (TM * AST * 2)
#define BSZ (TK * BST * 2)

template <int MODE>
__global__ __launch_bounds__(256, 2) void h16_gemm(   // cap regs at 128 -> 2 CTAs/SM
    const __half* __restrict__ A,
    const __half* __restrict__ Bq, const __half* __restrict__ Bk,
    const __half* __restrict__ Bv,
    float* __restrict__ Cout, float* __restrict__ nK, float* __restrict__ nV,
    __half* __restrict__ Hq, __half* __restrict__ Hk, __half* __restrict__ Hv,
    const float* __restrict__ cosp, const float* __restrict__ sinp,
    int M, int K)
{
    __shared__ __align__(16) __half As[STG][TM][AST];
    __shared__ __align__(16) __half Bs[STG][TK][BST];

    int bx = blockIdx.x;
    const __half* B;
    int N, nbx, sub;           // sub: 0=Q, 1=K, 2=V (MODE 3 only)
    if (MODE == 0) {
        B = Bq; N = EMB; nbx = bx; sub = 0;
    } else {
        if (bx < 16)      { B = Bq; N = EMB;      nbx = bx;      sub = 0; }
        else if (bx < 20) { B = Bk; N = NKV * HD; nbx = bx - 16; sub = 1; }
        else              { B = Bv; N = NKV * HD; nbx = bx - 20; sub = 2; }
    }

    int tid = threadIdx.x, lane = tid & 31, wid = tid >> 5;
    int wm = wid & 3, wn = wid >> 2;
    int g = lane >> 2, tg = lane & 3;

    const __half* Ab = A + (size_t)blockIdx.y * TM * K;
    const __half* Bb = B + (size_t)nbx * TN;

    float acc[2][8][4];
#pragma unroll
    for (int i = 0; i < 2; i++)
#pragma unroll
        for (int j = 0; j < 8; j++)
#pragma unroll
            for (int r = 0; r < 4; r++) acc[i][j][r] = 0.f;

    int ar0 = tid >> 2, ac0 = (tid & 3) * 8;
    int ar1 = (tid + 256) >> 2, ac1 = ((tid + 256) & 3) * 8;
    int br0 = tid >> 4, bc0 = (tid & 15) * 8;
    int br1 = (tid + 256) >> 4, bc1 = ((tid + 256) & 15) * 8;
    uint32_t aD0 = smem_u32(&As[0][ar0][ac0]);
    uint32_t aD1 = smem_u32(&As[0][ar1][ac1]);
    uint32_t bD0 = smem_u32(&Bs[0][br0][bc0]);
    uint32_t bD1 = smem_u32(&Bs[0][br1][bc1]);

    uint32_t aAddr[2], bAddr[4];
    {
        int arow = wm * 32 + (lane & 15);
        int acol = (lane >> 4) * 8;
        aAddr[0] = smem_u32(&As[0][arow][acol]);
        aAddr[1] = smem_u32(&As[0][arow + 16][acol]);
        int brow = ((lane >> 3) & 1) * 8 + (lane & 7);
        int bcol = wn * 64 + ((lane >> 4) & 1) * 8;
#pragma unroll
        for (int nb = 0; nb < 4; nb++)
            bAddr[nb] = smem_u32(&Bs[0][brow][bcol + nb * 16]);
    }

    int nt = K / TK;

#pragma unroll
    for (int p = 0; p < 2; p++) {
        int k0 = p * TK;
        cp16(aD0 + p * ASZ, Ab + (size_t)ar0 * K + k0 + ac0);
        cp16(aD1 + p * ASZ, Ab + (size_t)ar1 * K + k0 + ac1);
        cp16(bD0 + p * BSZ, Bb + (size_t)(k0 + br0) * N + bc0);
        cp16(bD1 + p * BSZ, Bb + (size_t)(k0 + br1) * N + bc1);
        cp_commit();
    }

    int st = 0;
    for (int t = 0; t < nt; t++) {
        cp_wait<1>();
        __syncthreads();

        uint32_t aOff = (uint32_t)(st * ASZ);
        uint32_t bOff = (uint32_t)(st * BSZ);
#pragma unroll
        for (int ks = 0; ks < 2; ks++) {
            uint32_t af[2][4];
            ldsm_x4(af[0][0], af[0][1], af[0][2], af[0][3], aAddr[0] + aOff + ks * 32);
            ldsm_x4(af[1][0], af[1][1], af[1][2], af[1][3], aAddr[1] + aOff + ks * 32);
            uint32_t bf[8][2];
#pragma unroll
            for (int nb = 0; nb < 4; nb++) {
                uint32_t r0, r1, r2, r3;
                ldsm_x4t(r0, r1, r2, r3, bAddr[nb] + bOff + ks * (16 * BST * 2));
                bf[2 * nb][0] = r0; bf[2 * nb][1] = r1;
                bf[2 * nb + 1][0] = r2; bf[2 * nb + 1][1] = r3;
            }
#pragma unroll
            for (int mf = 0; mf < 2; mf++)
#pragma unroll
                for (int fn = 0; fn < 8; fn++)
                    mma_f16(acc[mf][fn], af[mf][0], af[mf][1], af[mf][2], af[mf][3],
                            bf[fn][0], bf[fn][1]);
        }
        __syncthreads();   // phase separation (R9-proven structure)

        if (t + 2 < nt) {
            int ns = (st + 2) % STG;
            int k0 = (t + 2) * TK;
            cp16(aD0 + ns * ASZ, Ab + (size_t)ar0 * K + k0 + ac0);
            cp16(aD1 + ns * ASZ, Ab + (size_t)ar1 * K + k0 + ac1);
            cp16(bD0 + ns * BSZ, Bb + (size_t)(k0 + br0) * N + bc0);
            cp16(bD1 + ns * BSZ, Bb + (size_t)(k0 + br1) * N + bc1);
        }
        cp_commit();
        st = (st + 1) % STG;
    }

    // ---------------- epilogues ----------------
    if (MODE == 0) {
#pragma unroll
        for (int mf = 0; mf < 2; mf++) {
            int row0 = blockIdx.y * TM + wm * 32 + mf * 16 + g;
#pragma unroll
            for (int fn = 0; fn < 8; fn++) {
                int col = nbx * TN + wn * 64 + fn * 8 + tg * 2;
                *(float2*)&Cout[(size_t)row0 * N + col] =
                    make_float2(acc[mf][fn][0], acc[mf][fn][1]);
                *(float2*)&Cout[(size_t)(row0 + 8) * N + col] =
                    make_float2(acc[mf][fn][2], acc[mf][fn][3]);
            }
        }
    } else if (sub == 0) {
        // Q: RoPE + QSCALE, fp16 out. Pairs: acc[][fn] (d) with acc[][fn+4] (d+32).
        int colb = nbx * TN + wn * 64;
#pragma unroll
        for (int mf = 0; mf < 2; mf++) {
            int row0 = blockIdx.y * TM + wm * 32 + mf * 16 + g;
            int sA = row0 & (SEQ - 1);
            int sB = sA + 8;
#pragma unroll
            for (int fn = 0; fn < 4; fn++) {
                int d0 = fn * 8 + tg * 2;
                float2 cA = *(const float2*)&cosp[sA * HD + d0];
                float2 nA = *(const float2*)&sinp[sA * HD + d0];
                float2 cB = *(const float2*)&cosp[sB * HD + d0];
                float2 nB = *(const float2*)&sinp[sB * HD + d0];
                float x10 = acc[mf][fn][0], x11 = acc[mf][fn][1];
                float x20 = acc[mf][fn + 4][0], x21 = acc[mf][fn + 4][1];
                __half2 lo = __floats2half2_rn((x10 * cA.x - x20 * nA.x) * QSCALE,
                                               (x11 * cA.y - x21 * nA.y) * QSCALE);
                __half2 hi = __floats2half2_rn((x20 * cA.x + x10 * nA.x) * QSCALE,
                                               (x21 * cA.y + x11 * nA.y) * QSCALE);
                *(__half2*)&Hq[(size_t)row0 * EMB + colb + d0]      = lo;
                *(__half2*)&Hq[(size_t)row0 * EMB + colb + d0 + 32] = hi;
                x10 = acc[mf][fn][2]; x11 = acc[mf][fn][3];
                x20 = acc[mf][fn + 4][2]; x21 = acc[mf][fn + 4][3];
                lo = __floats2half2_rn((x10 * cB.x - x20 * nB.x) * QSCALE,
                                       (x11 * cB.y - x21 * nB.y) * QSCALE);
                hi = __floats2half2_rn((x20 * cB.x + x10 * nB.x) * QSCALE,
                                       (x21 * cB.y + x11 * nB.y) * QSCALE);
                *(__half2*)&Hq[(size_t)(row0 + 8) * EMB + colb + d0]      = lo;
                *(__half2*)&Hq[(size_t)(row0 + 8) * EMB + colb + d0 + 32] = hi;
            }
        }
    } else {
        // KV: transpose (B,S,KV,D)->(B,KV,S,D); sub==1 rope (K), sub==2 plain (V).
        float* Cz  = (sub == 1) ? nK : nV;
        __half* Hz = (sub == 1) ? Hk : Hv;
        bool dorope = (sub == 1);
        int colb = nbx * TN + wn * 64;
        int kvh = colb >> 6;
#pragma unroll
        for (int mf = 0; mf < 2; mf++) {
            int row0 = blockIdx.y * TM + wm * 32 + mf * 16 + g;
            int sA = row0 & (SEQ - 1);
            int bA = row0 >> 11;
            size_t oA = (((size_t)bA * NKV + kvh) * SEQ + sA) * HD;
            size_t oB = oA + (size_t)8 * HD;
#pragma unroll
            for (int fn = 0; fn < 4; fn++) {
                int d0 = fn * 8 + tg * 2;
                float r0, r1, r2, r3, q0, q1, q2, q3;
                if (dorope) {
                    float2 cA = *(const float2*)&cosp[sA * HD + d0];
                    float2 nA = *(const float2*)&sinp[sA * HD + d0];
                    float2 cB = *(const float2*)&cosp[(sA + 8) * HD + d0];
                    float2 nB = *(const float2*)&sinp[(sA + 8) * HD + d0];
                    r0 = acc[mf][fn][0] * cA.x - acc[mf][fn + 4][0] * nA.x;
                    r1 = acc[mf][fn][1] * cA.y - acc[mf][fn + 4][1] * nA.y;
                    r2 = acc[mf][fn + 4][0] * cA.x + acc[mf][fn][0] * nA.x;
                    r3 = acc[mf][fn + 4][1] * cA.y + acc[mf][fn][1] * nA.y;
                    q0 = acc[mf][fn][2] * cB.x - acc[mf][fn + 4][2] * nB.x;
                    q1 = acc[mf][fn][3] * cB.y - acc[mf][fn + 4][3] * nB.y;
                    q2 = acc[mf][fn + 4][2] * cB.x + acc[mf][fn][2] * nB.x;
                    q3 = acc[mf][fn + 4][3] * cB.y + acc[mf][fn][3] * nB.y;
                } else {
                    r0 = acc[mf][fn][0]; r1 = acc[mf][fn][1];
                    r2 = acc[mf][fn + 4][0]; r3 = acc[mf][fn + 4][1];
                    q0 = acc[mf][fn][2]; q1 = acc[mf][fn][3];
                    q2 = acc[mf][fn + 4][2]; q3 = acc[mf][fn + 4][3];
                }
                *(float2*)&Cz[oA + d0]      = make_float2(r0, r1);
                *(float2*)&Cz[oA + d0 + 32] = make_float2(r2, r3);
                *(float2*)&Cz[oB + d0]      = make_float2(q0, q1);
                *(float2*)&Cz[oB + d0 + 32] = make_float2(q2, q3);
                *(__half2*)&Hz[oA + d0]      = __floats2half2_rn(r0, r1);
                *(__half2*)&Hz[oA + d0 + 32] = __floats2half2_rn(r2, r3);
                *(__half2*)&Hz[oB + d0]      = __floats2half2_rn(q0, q1);
                *(__half2*)&Hz[oB + d0 + 32] = __floats2half2_rn(q2, q3);
            }
        }
    }
}

// ---------------- Tensor-core flash attention (causal, base-2 softmax) -------
// grid (S/128, NH, B), 256 threads. Longest blocks (high qt) launch first.
#define QTILE 128
#define KTILE 64
#define QST 72
#define KSTGB (KTILE * QST * 2)
#define ATTN_SMEM ((QTILE + 4 * KTILE) * QST * 2)  // 55296 B

__global__ __launch_bounds__(256) void attn_h16(
    const __half* __restrict__ q,
    const __half* __restrict__ kk,
    const __half* __restrict__ vv,
    __half* __restrict__ out)
{
    extern __shared__ __align__(16) __half sm[];
    __half (*Qh)[QST] = (__half(*)[QST])sm;
    __half (*Ks)[QST] = (__half(*)[QST])(sm + QTILE * QST);
    __half (*Vs)[QST] = (__half(*)[QST])(sm + (QTILE + 2 * KTILE) * QST);

    int qt = gridDim.x - 1 - blockIdx.x;   // longest work first
    int h = blockIdx.y, b = blockIdx.z;
    int kv = h >> 2;
    int tid = threadIdx.x, lane = tid & 31, w = tid >> 5;
    int g = lane >> 2, tg = lane & 3;

    const __half* qbase = q + (((size_t)b * SEQ + (size_t)qt * QTILE) * NH + h) * HD;
    const __half* kbase = kk + ((size_t)b * NKV + kv) * SEQ * HD;
    const __half* vbase = vv + ((size_t)b * NKV + kv) * SEQ * HD;

    int kr0 = tid >> 3, kc0 = (tid & 7) * 8;
    int kr1 = (tid + 256) >> 3, kc1 = ((tid + 256) & 7) * 8;
    uint32_t ksD0 = smem_u32(&Ks[kr0][kc0]), ksD1 = smem_u32(&Ks[kr1][kc1]);
    uint32_t vsD0 = smem_u32(&Vs[kr0][kc0]), vsD1 = smem_u32(&Vs[kr1][kc1]);

    int nk = 2 * qt + 2;

#pragma unroll
    for (int i = 0; i < 4; i++) {
        int c = tid + i * 256;
        int r = c >> 3, col = (c & 7) * 8;
        cp16(smem_u32(&Qh[r][col]), qbase + (size_t)r * NH * HD + col);
    }
    {
        cp16(ksD0, kbase + (size_t)kr0 * HD + kc0);
        cp16(ksD1, kbase + (size_t)kr1 * HD + kc1);
        cp16(vsD0, vbase + (size_t)kr0 * HD + kc0);
        cp16(vsD1, vbase + (size_t)kr1 * HD + kc1);
    }
    cp_commit();
    {
        const __half* kp = kbase + (size_t)KTILE * HD;
        const __half* vp = vbase + (size_t)KTILE * HD;
        cp16(ksD0 + KSTGB, kp + (size_t)kr0 * HD + kc0);
        cp16(ksD1 + KSTGB, kp + (size_t)kr1 * HD + kc1);
        cp16(vsD0 + KSTGB, vp + (size_t)kr0 * HD + kc0);
        cp16(vsD1 + KSTGB, vp + (size_t)kr1 * HD + kc1);
    }
    cp_commit();

    uint32_t kAddr[4], vAddr[4], qAddr;
    {
        int krow = (lane & 15), kcol = (lane >> 4) * 8;
#pragma unroll
        for (int nb = 0; nb < 4; nb++)
            kAddr[nb] = smem_u32(&Ks[nb * 16 + krow][kcol]);
        int vrow = ((lane >> 3) & 1) * 8 + (lane & 7);
        int vcol = ((lane >> 4) & 1) * 8;
#pragma unroll
        for (int nb = 0; nb < 4; nb++)
            vAddr[nb] = smem_u32(&Vs[vrow][vcol + nb * 16]);
        int arow = w * 16 + (lane & 15), acol = (lane >> 4) * 8;
        qAddr = smem_u32(&Qh[arow][acol]);
    }

    uint32_t aqh[4][4];
    float oacc[8][4];
#pragma unroll
    for (int fn = 0; fn < 8; fn++)
#pragma unroll
        for (int r = 0; r < 4; r++) oacc[fn][r] = 0.f;
    float m0 = -1e30f, m1 = -1e30f, l0 = 0.f, l1 = 0.f;

    int r0loc = w * 16 + g;
    int rg0 = qt * QTILE + r0loc;
    int rg1 = rg0 + 8;

    for (int kt = 0; kt < nk; kt++) {
        cp_wait<1>();
        __syncthreads();

        if (kt == 0) {
#pragma unroll
            for (int ks = 0; ks < 4; ks++)
                ldsm_x4(aqh[ks][0], aqh[ks][1], aqh[ks][2], aqh[ks][3], qAddr + ks * 32);
        }

        uint32_t so = (uint32_t)((kt & 1) * KSTGB);

        float s[8][4];
#pragma unroll
        for (int fn = 0; fn < 8; fn++)
#pragma unroll
            for (int r = 0; r < 4; r++) s[fn][r] = 0.f;

#pragma unroll
        for (int ks = 0; ks < 4; ks++) {
            uint32_t kb[8][2];
#pragma unroll
            for (int nb = 0; nb < 4; nb++) {
                uint32_t r0, r1, r2, r3;
                ldsm_x4(r0, r1, r2, r3, kAddr[nb] + so + ks * 32);
                kb[2 * nb][0] = r0; kb[2 * nb + 1][0] = r1;
                kb[2 * nb][1] = r2; kb[2 * nb + 1][1] = r3;
            }
#pragma unroll
            for (int fn = 0; fn < 8; fn++)
                mma_f16(s[fn], aqh[ks][0], aqh[ks][1], aqh[ks][2], aqh[ks][3],
                        kb[fn][0], kb[fn][1]);
        }

        if (kt >= 2 * qt) {
            int cb = kt * KTILE;
#pragma unroll
            for (int fn = 0; fn < 8; fn++) {
                int c = cb + fn * 8 + 2 * tg;
                if (c > rg0)     s[fn][0] = -1e30f;
                if (c + 1 > rg0) s[fn][1] = -1e30f;
                if (c > rg1)     s[fn][2] = -1e30f;
                if (c + 1 > rg1) s[fn][3] = -1e30f;
            }
        }

        float mx0 = -1e30f, mx1 = -1e30f;
#pragma unroll
        for (int fn = 0; fn < 8; fn++) {
            mx0 = fmaxf(mx0, fmaxf(s[fn][0], s[fn][1]));
            mx1 = fmaxf(mx1, fmaxf(s[fn][2], s[fn][3]));
        }
        mx0 = fmaxf(mx0, __shfl_xor_sync(0xffffffffu, mx0, 1));
        mx0 = fmaxf(mx0, __shfl_xor_sync(0xffffffffu, mx0, 2));
        mx1 = fmaxf(mx1, __shfl_xor_sync(0xffffffffu, mx1, 1));
        mx1 = fmaxf(mx1, __shfl_xor_sync(0xffffffffu, mx1, 2));
        float mn0 = fmaxf(m0, mx0), mn1 = fmaxf(m1, mx1);
        float c0 = exp2f(m0 - mn0), c1 = exp2f(m1 - mn1);
        m0 = mn0; m1 = mn1;

        float su0 = 0.f, su1 = 0.f;
        uint32_t pA[4][4];
#pragma unroll
        for (int fn = 0; fn < 8; fn++) {
            float e0 = exp2f(s[fn][0] - mn0);
            float e1 = exp2f(s[fn][1] - mn0);
            float e2 = exp2f(s[fn][2] - mn1);
            float e3 = exp2f(s[fn][3] - mn1);
            su0 += e0 + e1;
            su1 += e2 + e3;
            __half2 p01 = __floats2half2_rn(e0, e1);
            __half2 p23 = __floats2half2_rn(e2, e3);
            int kq = fn >> 1;
            int hi = (fn & 1) * 2;
            pA[kq][hi]     = *(uint32_t*)&p01;
            pA[kq][hi + 1] = *(uint32_t*)&p23;
        }
        su0 += __shfl_xor_sync(0xffffffffu, su0, 1);
        su0 += __shfl_xor_sync(0xffffffffu, su0, 2);
        su1 += __shfl_xor_sync(0xffffffffu, su1, 1);
        su1 += __shfl_xor_sync(0xffffffffu, su1, 2);
        l0 = l0 * c0 + su0;
        l1 = l1 * c1 + su1;

#pragma unroll
        for (int fn = 0; fn < 8; fn++) {
            oacc[fn][0] *= c0; oacc[fn][1] *= c0;
            oacc[fn][2] *= c1; oacc[fn][3] *= c1;
        }

#pragma unroll
        for (int kq = 0; kq < 4; kq++) {
            uint32_t vb[8][2];
#pragma unroll
            for (int nb = 0; nb < 4; nb++) {
                uint32_t r0, r1, r2, r3;
                ldsm_x4t(r0, r1, r2, r3, vAddr[nb] + so + kq * (16 * QST * 2));
                vb[2 * nb][0] = r0; vb[2 * nb][1] = r1;
                vb[2 * nb + 1][0] = r2; vb[2 * nb + 1][1] = r3;
            }
#pragma unroll
            for (int fn = 0; fn < 8; fn++)
                mma_f16(oacc[fn], pA[kq][0], pA[kq][1], pA[kq][2], pA[kq][3],
                        vb[fn][0], vb[fn][1]);
        }

        __syncthreads();
        if (kt + 2 < nk) {
            const __half* kp = kbase + (size_t)(kt + 2) * KTILE * HD;
            const __half* vp = vbase + (size_t)(kt + 2) * KTILE * HD;
            uint32_t ds = (uint32_t)((kt & 1) * KSTGB);
            cp16(ksD0 + ds, kp + (size_t)kr0 * HD + kc0);
            cp16(ksD1 + ds, kp + (size_t)kr1 * HD + kc1);
            cp16(vsD0 + ds, vp + (size_t)kr0 * HD + kc0);
            cp16(vsD1 + ds, vp + (size_t)kr1 * HD + kc1);
        }
        cp_commit();
    }

    float inv0 = 1.f / l0, inv1 = 1.f / l1;
    __half* ob = out + (((size_t)b * SEQ + rg0) * NH + h) * HD;
#pragma unroll
    for (int fn = 0; fn < 8; fn++) {
        int c = fn * 8 + 2 * tg;
        __half2 lo = __floats2half2_rn(oacc[fn][0] * inv0, oacc[fn][1] * inv0);
        __half2 hi = __floats2half2_rn(oacc[fn][2] * inv1, oacc[fn][3] * inv1);
        *(__half2*)(ob + c) = lo;
        *(__half2*)(ob + (size_t)8 * NH * HD + c) = hi;
    }
}

// ---------------- launch -----------------------------------------------------
extern "C" void kernel_launch(void* const* d_in, const int* in_sizes, int n_in,
                              void* d_out, int out_size)
{
    const float* x    = (const float*)d_in[0];
    // d_in[1] = mask (causal) — analytic
    const float* cosp = (const float*)d_in[2];
    const float* sinp = (const float*)d_in[3];
    const float* Wq   = (const float*)d_in[4];
    const float* Wk   = (const float*)d_in[5];
    const float* Wv   = (const float*)d_in[6];
    const float* Wo   = (const float*)d_in[7];

    float* out    = (float*)d_out;
    float* next_k = out + (size_t)Bsz * SEQ * EMB;
    float* next_v = next_k + (size_t)Bsz * NKV * SEQ * HD;

    __half *xh, *wqh, *wkh, *wvh, *woh, *qh, *kh, *vh, *ah;
    cudaGetSymbolAddress((void**)&xh,  g_xh);
    cudaGetSymbolAddress((void**)&wqh, g_wqh);
    cudaGetSymbolAddress((void**)&wkh, g_wkh);
    cudaGetSymbolAddress((void**)&wvh, g_wvh);
    cudaGetSymbolAddress((void**)&woh, g_woh);
    cudaGetSymbolAddress((void**)&qh,  g_qh);
    cudaGetSymbolAddress((void**)&kh,  g_kh);
    cudaGetSymbolAddress((void**)&vh,  g_vh);
    cudaGetSymbolAddress((void**)&ah,  g_ah);

    static bool cfg = false;
    if (!cfg) {
        cudaFuncSetAttribute(attn_h16, cudaFuncAttributeMaxDynamicSharedMemorySize,
                             ATTN_SMEM);
        cfg = true;
    }

    // fp32 -> fp16 conversions (single segmented launch)
    cvt5<<<dim3(1024, 5), 256>>>(x, xh, BSxS * EMB,
                                 Wq, wqh, EMB * EMB,
                                 Wk, wkh, EMB * NKV * HD,
                                 Wv, wvh, EMB * NKV * HD,
                                 Wo, woh, EMB * EMB);

    // Fused Q + K + V projection (RoPE/transpose in epilogues)
    h16_gemm<3><<<dim3(24, BSxS / TM), 256>>>(
        xh, wqh, wkh, wvh, nullptr, next_k, next_v, qh, kh, vh,
        cosp, sinp, BSxS, EMB);

    // Flash attention (base-2 softmax)
    attn_h16<<<dim3(SEQ / QTILE, NH, Bsz), 256, ATTN_SMEM>>>(qh, kh, vh, ah);

    // Output projection (plain fp32 epilogue)
    h16_gemm<0><<<dim3(EMB / TN, BSxS / TM), 256>>>(
        ah, woh, nullptr, nullptr, out, nullptr, nullptr, nullptr, nullptr, nullptr,
        nullptr, nullptr, BSxS, EMB);
}